// round 6
// baseline (speedup 1.0000x reference)
#include <cuda_runtime.h>

#define NN 100000
#define NE 800000
#define C 64
#define H 4
#define NB_SCAN 98   // ceil(NN/1024)

// ---- scratch (allocation-free: __device__ globals) ----
__device__ float g_h[NN * C];         // h = xW + b
__device__ float g_a[NN * 8];         // a_src[0..3], a_dst[0..3]
__device__ int   g_cnt[NN];           // in-degree histogram
__device__ int   g_off[NN + 1];       // CSR offsets
__device__ int   g_cur[NN];           // scatter cursors
__device__ int   g_btot[NB_SCAN];     // scan block totals
__device__ int   g_csrc[NE];          // CSR: src per slot
__device__ float g_ce[NE * 4];        // CSR: exp-scores per slot (float4)
__device__ int   g_idx64;

__device__ __forceinline__ int edge_idx(const void* ei, long long pos) {
    if (g_idx64) return (int)((const long long*)ei)[pos];
    return ((const int*)ei)[pos];
}

// ---- fused: dtype probe + zero histogram ----
__global__ void k_init(const void* ei) {
    int i = blockIdx.x * blockDim.x + threadIdx.x;
    if (i < NN) g_cnt[i] = 0;
    if (i == 0) {
        const long long* p = (const long long*)ei;
        bool ok = true;
        for (int k = 0; k < 4; k++) {
            long long v = p[k];
            if (v < 0 || v >= NN) ok = false;
        }
        g_idx64 = ok ? 1 : 0;
    }
}

// ---- node precompute: h = xW+b ; a = h @ attn_w ----
#define ROWS_K1 16
__global__ __launch_bounds__(256) void k_node(const float* __restrict__ x,
                                              const float* __restrict__ Ww,
                                              const float* __restrict__ Wb,
                                              const float* __restrict__ aw) {
    __shared__ float xs[ROWS_K1][C];
    __shared__ float hs[ROWS_K1][C];
    const int base = blockIdx.x * ROWS_K1;
    const int t = threadIdx.x;

#pragma unroll
    for (int k = 0; k < 4; k++) {
        int idx = t + k * 256;
        xs[idx >> 6][idx & 63] = x[(base + (idx >> 6)) * C + (idx & 63)];
    }
    __syncthreads();

    {
        int j = t & 63;
        int r0 = (t >> 6) * 4;
        float a0 = 0.f, a1 = 0.f, a2 = 0.f, a3 = 0.f;
#pragma unroll 8
        for (int c = 0; c < C; c++) {
            float w = __ldg(&Ww[c * C + j]);
            a0 = fmaf(xs[r0 + 0][c], w, a0);
            a1 = fmaf(xs[r0 + 1][c], w, a1);
            a2 = fmaf(xs[r0 + 2][c], w, a2);
            a3 = fmaf(xs[r0 + 3][c], w, a3);
        }
        float b = __ldg(&Wb[j]);
        a0 += b; a1 += b; a2 += b; a3 += b;
        hs[r0 + 0][j] = a0; hs[r0 + 1][j] = a1;
        hs[r0 + 2][j] = a2; hs[r0 + 3][j] = a3;
        g_h[(base + r0 + 0) * C + j] = a0;
        g_h[(base + r0 + 1) * C + j] = a1;
        g_h[(base + r0 + 2) * C + j] = a2;
        g_h[(base + r0 + 3) * C + j] = a3;
    }
    __syncthreads();

    if (t < 128) {
        int r = t >> 3, k = t & 7;
        int hh = k & 3;
        int off = (k < 4) ? 0 : C;
        float acc = 0.f;
#pragma unroll 8
        for (int c = 0; c < C; c++)
            acc = fmaf(hs[r][c], __ldg(&aw[(off + c) * H + hh]), acc);
        g_a[(base + r) * 8 + k] = acc;
    }
}

// ---- in-degree histogram ----
__global__ __launch_bounds__(256) void k_hist(const void* __restrict__ ei) {
    int e = blockIdx.x * blockDim.x + threadIdx.x;
    if (e >= NE) return;
    int dst = edge_idx(ei, (long long)NE + e);
    atomicAdd(&g_cnt[dst], 1);
}

// ---- scan phase A ----
__global__ __launch_bounds__(1024) void k_scanA() {
    __shared__ int sh[1024];
    int b = blockIdx.x, t = threadIdx.x;
    int idx = b * 1024 + t;
    int v = (idx < NN) ? g_cnt[idx] : 0;
    sh[t] = v;
    __syncthreads();
#pragma unroll
    for (int o = 1; o < 1024; o <<= 1) {
        int x = (t >= o) ? sh[t - o] : 0;
        __syncthreads();
        sh[t] += x;
        __syncthreads();
    }
    if (idx < NN) g_off[idx] = sh[t] - v;
    if (t == 1023) g_btot[b] = sh[1023];
}

// ---- scan phase B ----
__global__ __launch_bounds__(1024) void k_scanB() {
    __shared__ int bt[NB_SCAN];
    int b = blockIdx.x, t = threadIdx.x;
    if (t < NB_SCAN) bt[t] = g_btot[t];
    __syncthreads();
    int s = 0;
    for (int i = 0; i < b; i++) s += bt[i];
    int idx = b * 1024 + t;
    if (idx < NN) {
        int o = g_off[idx] + s;
        g_off[idx] = o;
        g_cur[idx] = o;
    }
    if (b == 0 && t == 0) g_off[NN] = NE;
}

// ---- fused score + CSR scatter ----
__global__ __launch_bounds__(256) void k_scatter(const void* __restrict__ ei,
                                                 const float* __restrict__ et,
                                                 const int* __restrict__ ct,
                                                 const float* __restrict__ ab,
                                                 const float* __restrict__ dr) {
    int e = blockIdx.x * blockDim.x + threadIdx.x;
    if (e >= NE) return;
    int src = edge_idx(ei, e);
    int dst = edge_idx(ei, (long long)NE + e);

    float lam = log1pf(__expf(dr[0]));            // softplus
    float dt = (float)ct[0] - et[e];
    float decay = __expf(-lam * dt);

    float4 as = *(const float4*)&g_a[src * 8];
    float4 ad = *(const float4*)&g_a[dst * 8 + 4];
    float s[4];
    s[0] = as.x + ad.x + __ldg(&ab[0]);
    s[1] = as.y + ad.y + __ldg(&ab[1]);
    s[2] = as.z + ad.z + __ldg(&ab[2]);
    s[3] = as.w + ad.w + __ldg(&ab[3]);
#pragma unroll
    for (int h = 0; h < 4; h++) {
        float l = s[h];
        l = (l > 0.f) ? l : 0.2f * l;             // LeakyReLU(0.2)
        s[h] = __expf(l * decay);
    }
    int pos = atomicAdd(&g_cur[dst], 1);
    g_csrc[pos] = src;
    *(float4*)&g_ce[pos * 4] = make_float4(s[0], s[1], s[2], s[3]);
}

// ---- FUSED aggregation + projection GEMM + bias/residual/LN/ReLU ----
// 32 nodes/block. Agg: 8 warps each take an equal 1/8 slice of the block's
// CSR edge range (load-balanced), accumulate in regs, flush at node
// boundaries via smem atomics. us[r][256..259] hold per-head exp-sums.
#define TB 32
#define UPAD 260
__global__ __launch_bounds__(256) void k_aggemm(const float* __restrict__ pw,
                                                const float* __restrict__ pb,
                                                const float* __restrict__ x,
                                                const float* __restrict__ lg,
                                                const float* __restrict__ lb,
                                                float* __restrict__ out) {
    __shared__ float us[TB][UPAD];
    __shared__ float ws[32][68];
    __shared__ int offs[TB + 1];
    const int t = threadIdx.x;
    const int w = t >> 5, lane = t & 31;
    const int base = blockIdx.x * TB;

    // zero us, stage offsets
    if (t <= TB) offs[t] = g_off[base + t];
#pragma unroll
    for (int i = 0; i < 33; i++) {
        int idx = i * 256 + t;
        if (idx < TB * UPAD) ((float*)us)[idx] = 0.f;
    }
    __syncthreads();

    // ---- phase 1: balanced cooperative aggregation ----
    {
        const int ebeg = offs[0], eend = offs[TB];
        const int total = eend - ebeg;
        const int per = (total + 7) >> 3;
        int sbeg = ebeg + min(w * per, total);
        const int send = ebeg + min((w + 1) * per, total);

        if (sbeg < send) {
            int n = 0;
            while (offs[n + 1] <= sbeg) n++;
            int i = sbeg;
            while (true) {
                int stop = min(send, offs[n + 1]);
                float a00 = 0.f, a01 = 0.f, a10 = 0.f, a11 = 0.f;
                float a20 = 0.f, a21 = 0.f, a30 = 0.f, a31 = 0.f;
                float s0 = 0.f, s1 = 0.f, s2 = 0.f, s3 = 0.f;

                for (; i + 4 <= stop; i += 4) {
                    int sa = __ldg(&g_csrc[i]);
                    int sb = __ldg(&g_csrc[i + 1]);
                    int sc = __ldg(&g_csrc[i + 2]);
                    int sd = __ldg(&g_csrc[i + 3]);
                    float4 ea = __ldg((const float4*)&g_ce[i * 4]);
                    float4 eb = __ldg((const float4*)&g_ce[i * 4 + 4]);
                    float4 ec = __ldg((const float4*)&g_ce[i * 4 + 8]);
                    float4 ed = __ldg((const float4*)&g_ce[i * 4 + 12]);
                    float ha0 = __ldg(&g_h[sa * C + lane]);
                    float ha1 = __ldg(&g_h[sa * C + 32 + lane]);
                    float hb0 = __ldg(&g_h[sb * C + lane]);
                    float hb1 = __ldg(&g_h[sb * C + 32 + lane]);
                    float hc0 = __ldg(&g_h[sc * C + lane]);
                    float hc1 = __ldg(&g_h[sc * C + 32 + lane]);
                    float hd0 = __ldg(&g_h[sd * C + lane]);
                    float hd1 = __ldg(&g_h[sd * C + 32 + lane]);
                    a00 = fmaf(ea.x, ha0, a00); a01 = fmaf(ea.x, ha1, a01);
                    a10 = fmaf(ea.y, ha0, a10); a11 = fmaf(ea.y, ha1, a11);
                    a20 = fmaf(ea.z, ha0, a20); a21 = fmaf(ea.z, ha1, a21);
                    a30 = fmaf(ea.w, ha0, a30); a31 = fmaf(ea.w, ha1, a31);
                    s0 += ea.x; s1 += ea.y; s2 += ea.z; s3 += ea.w;
                    a00 = fmaf(eb.x, hb0, a00); a01 = fmaf(eb.x, hb1, a01);
                    a10 = fmaf(eb.y, hb0, a10); a11 = fmaf(eb.y, hb1, a11);
                    a20 = fmaf(eb.z, hb0, a20); a21 = fmaf(eb.z, hb1, a21);
                    a30 = fmaf(eb.w, hb0, a30); a31 = fmaf(eb.w, hb1, a31);
                    s0 += eb.x; s1 += eb.y; s2 += eb.z; s3 += eb.w;
                    a00 = fmaf(ec.x, hc0, a00); a01 = fmaf(ec.x, hc1, a01);
                    a10 = fmaf(ec.y, hc0, a10); a11 = fmaf(ec.y, hc1, a11);
                    a20 = fmaf(ec.z, hc0, a20); a21 = fmaf(ec.z, hc1, a21);
                    a30 = fmaf(ec.w, hc0, a30); a31 = fmaf(ec.w, hc1, a31);
                    s0 += ec.x; s1 += ec.y; s2 += ec.z; s3 += ec.w;
                    a00 = fmaf(ed.x, hd0, a00); a01 = fmaf(ed.x, hd1, a01);
                    a10 = fmaf(ed.y, hd0, a10); a11 = fmaf(ed.y, hd1, a11);
                    a20 = fmaf(ed.z, hd0, a20); a21 = fmaf(ed.z, hd1, a21);
                    a30 = fmaf(ed.w, hd0, a30); a31 = fmaf(ed.w, hd1, a31);
                    s0 += ed.x; s1 += ed.y; s2 += ed.z; s3 += ed.w;
                }
                for (; i < stop; i++) {
                    int sa = __ldg(&g_csrc[i]);
                    float4 ea = __ldg((const float4*)&g_ce[i * 4]);
                    float ha0 = __ldg(&g_h[sa * C + lane]);
                    float ha1 = __ldg(&g_h[sa * C + 32 + lane]);
                    a00 = fmaf(ea.x, ha0, a00); a01 = fmaf(ea.x, ha1, a01);
                    a10 = fmaf(ea.y, ha0, a10); a11 = fmaf(ea.y, ha1, a11);
                    a20 = fmaf(ea.z, ha0, a20); a21 = fmaf(ea.z, ha1, a21);
                    a30 = fmaf(ea.w, ha0, a30); a31 = fmaf(ea.w, ha1, a31);
                    s0 += ea.x; s1 += ea.y; s2 += ea.z; s3 += ea.w;
                }
                // flush node n
                atomicAdd(&us[n][0 * 64 + lane], a00);
                atomicAdd(&us[n][0 * 64 + 32 + lane], a01);
                atomicAdd(&us[n][1 * 64 + lane], a10);
                atomicAdd(&us[n][1 * 64 + 32 + lane], a11);
                atomicAdd(&us[n][2 * 64 + lane], a20);
                atomicAdd(&us[n][2 * 64 + 32 + lane], a21);
                atomicAdd(&us[n][3 * 64 + lane], a30);
                atomicAdd(&us[n][3 * 64 + 32 + lane], a31);
                if (lane == 0) {
                    atomicAdd(&us[n][256], s0);
                    atomicAdd(&us[n][257], s1);
                    atomicAdd(&us[n][258], s2);
                    atomicAdd(&us[n][259], s3);
                }
                if (i >= send) break;
                n++;
                while (offs[n + 1] <= i) n++;
            }
        }
    }
    __syncthreads();

    // ---- normalize: 8 threads per node, 32 values each (h constant/thread) ----
    {
        int r = t >> 3, sub = t & 7;
        int hh = sub >> 1;
        float rinv = 1.f / (us[r][256 + hh] + 1e-8f);
#pragma unroll
        for (int k = 0; k < 32; k++)
            us[r][sub * 32 + k] *= rinv;
    }
    __syncthreads();

    // ---- phase 2: GEMM 32x64, K=256 in chunks of 32 ----
    const int tx = t & 15, ty = t >> 4;
    float acc[2][4];
#pragma unroll
    for (int i = 0; i < 2; i++)
#pragma unroll
        for (int j = 0; j < 4; j++) acc[i][j] = 0.f;

    for (int kc = 0; kc < 8; kc++) {
#pragma unroll
        for (int rr = 0; rr < 2; rr++) {
            int kk = ty * 2 + rr;
            int q = kc * 32 + kk;
            int row = ((q & 63) << 2) + (q >> 6);
            float4 wv = __ldg((const float4*)&pw[row * 64 + tx * 4]);
            ws[kk][tx * 4 + 0] = wv.x; ws[kk][tx * 4 + 1] = wv.y;
            ws[kk][tx * 4 + 2] = wv.z; ws[kk][tx * 4 + 3] = wv.w;
        }
        __syncthreads();

#pragma unroll 8
        for (int k4 = 0; k4 < 8; k4++) {
            float4 a0 = *(const float4*)&us[ty * 2 + 0][kc * 32 + k4 * 4];
            float4 a1 = *(const float4*)&us[ty * 2 + 1][kc * 32 + k4 * 4];
            float4 b0 = *(const float4*)&ws[k4 * 4 + 0][tx * 4];
            float4 b1 = *(const float4*)&ws[k4 * 4 + 1][tx * 4];
            float4 b2 = *(const float4*)&ws[k4 * 4 + 2][tx * 4];
            float4 b3 = *(const float4*)&ws[k4 * 4 + 3][tx * 4];
            acc[0][0] = fmaf(a0.x, b0.x, acc[0][0]); acc[0][1] = fmaf(a0.x, b0.y, acc[0][1]);
            acc[0][2] = fmaf(a0.x, b0.z, acc[0][2]); acc[0][3] = fmaf(a0.x, b0.w, acc[0][3]);
            acc[1][0] = fmaf(a1.x, b0.x, acc[1][0]); acc[1][1] = fmaf(a1.x, b0.y, acc[1][1]);
            acc[1][2] = fmaf(a1.x, b0.z, acc[1][2]); acc[1][3] = fmaf(a1.x, b0.w, acc[1][3]);
            acc[0][0] = fmaf(a0.y, b1.x, acc[0][0]); acc[0][1] = fmaf(a0.y, b1.y, acc[0][1]);
            acc[0][2] = fmaf(a0.y, b1.z, acc[0][2]); acc[0][3] = fmaf(a0.y, b1.w, acc[0][3]);
            acc[1][0] = fmaf(a1.y, b1.x, acc[1][0]); acc[1][1] = fmaf(a1.y, b1.y, acc[1][1]);
            acc[1][2] = fmaf(a1.y, b1.z, acc[1][2]); acc[1][3] = fmaf(a1.y, b1.w, acc[1][3]);
            acc[0][0] = fmaf(a0.z, b2.x, acc[0][0]); acc[0][1] = fmaf(a0.z, b2.y, acc[0][1]);
            acc[0][2] = fmaf(a0.z, b2.z, acc[0][2]); acc[0][3] = fmaf(a0.z, b2.w, acc[0][3]);
            acc[1][0] = fmaf(a1.z, b2.x, acc[1][0]); acc[1][1] = fmaf(a1.z, b2.y, acc[1][1]);
            acc[1][2] = fmaf(a1.z, b2.z, acc[1][2]); acc[1][3] = fmaf(a1.z, b2.w, acc[1][3]);
            acc[0][0] = fmaf(a0.w, b3.x, acc[0][0]); acc[0][1] = fmaf(a0.w, b3.y, acc[0][1]);
            acc[0][2] = fmaf(a0.w, b3.z, acc[0][2]); acc[0][3] = fmaf(a0.w, b3.w, acc[0][3]);
            acc[1][0] = fmaf(a1.w, b3.x, acc[1][0]); acc[1][1] = fmaf(a1.w, b3.y, acc[1][1]);
            acc[1][2] = fmaf(a1.w, b3.z, acc[1][2]); acc[1][3] = fmaf(a1.w, b3.w, acc[1][3]);
        }
        __syncthreads();
    }

    // ---- epilogue ----
    float4 bias = __ldg((const float4*)&pb[tx * 4]);
#pragma unroll
    for (int i = 0; i < 2; i++) {
        int node = base + ty * 2 + i;
        float4 xv = *(const float4*)&x[node * 64 + tx * 4];
        ws[ty * 2 + i][tx * 4 + 0] = acc[i][0] + bias.x + xv.x;
        ws[ty * 2 + i][tx * 4 + 1] = acc[i][1] + bias.y + xv.y;
        ws[ty * 2 + i][tx * 4 + 2] = acc[i][2] + bias.z + xv.z;
        ws[ty * 2 + i][tx * 4 + 3] = acc[i][3] + bias.w + xv.w;
    }
    __syncthreads();

#pragma unroll
    for (int rr = 0; rr < 4; rr++) {
        int row = w * 4 + rr;
        int node = base + row;
        float z0 = ws[row][lane];
        float z1 = ws[row][32 + lane];
        float s = z0 + z1;
#pragma unroll
        for (int o = 16; o; o >>= 1) s += __shfl_xor_sync(0xffffffffu, s, o);
        float mu = s * (1.f / 64.f);
        float d0 = z0 - mu, d1 = z1 - mu;
        float v = d0 * d0 + d1 * d1;
#pragma unroll
        for (int o = 16; o; o >>= 1) v += __shfl_xor_sync(0xffffffffu, v, o);
        float inv = rsqrtf(v * (1.f / 64.f) + 1e-5f);
        float y0 = __ldg(&lg[lane])      * d0 * inv + __ldg(&lb[lane]);
        float y1 = __ldg(&lg[32 + lane]) * d1 * inv + __ldg(&lb[32 + lane]);
        out[node * 64 + lane]      = fmaxf(y0, 0.f);
        out[node * 64 + 32 + lane] = fmaxf(y1, 0.f);
    }
}

extern "C" void kernel_launch(void* const* d_in, const int* in_sizes, int n_in,
                              void* d_out, int out_size) {
    const float* x  = (const float*)d_in[0];
    const void*  ei = d_in[1];
    const float* et = (const float*)d_in[2];
    const int*   ct = (const int*)d_in[3];
    const float* Ww = (const float*)d_in[4];
    const float* Wb = (const float*)d_in[5];
    const float* aw = (const float*)d_in[6];
    const float* ab = (const float*)d_in[7];
    const float* dr = (const float*)d_in[8];
    const float* pw = (const float*)d_in[9];
    const float* pb = (const float*)d_in[10];
    const float* lg = (const float*)d_in[11];
    const float* lb = (const float*)d_in[12];
    float* out = (float*)d_out;

    k_init<<<(NN + 255) / 256, 256>>>(ei);
    k_node<<<NN / ROWS_K1, 256>>>(x, Ww, Wb, aw);
    k_hist<<<NE / 256, 256>>>(ei);
    k_scanA<<<NB_SCAN, 1024>>>();
    k_scanB<<<NB_SCAN, 1024>>>();
    k_scatter<<<NE / 256, 256>>>(ei, et, ct, ab, dr);
    k_aggemm<<<NN / TB, 256>>>(pw, pb, x, lg, lb, out);
}

// round 7
// speedup vs baseline: 1.2509x; 1.2509x over previous
#include <cuda_runtime.h>

#define NN 100000
#define NE 800000
#define C 64
#define H 4
#define NB_SCAN 98   // ceil(NN/1024)

// ---- scratch (allocation-free: __device__ globals) ----
__device__ float g_h[NN * C];         // h = xW + b
__device__ float g_a[NN * 8];         // a_src[0..3], a_dst[0..3]
__device__ int   g_cnt[NN];           // in-degree histogram
__device__ int   g_off[NN + 1];       // CSR offsets
__device__ int   g_cur[NN];           // scatter cursors
__device__ int   g_btot[NB_SCAN];     // scan block totals
__device__ int   g_csrc[NE];          // CSR: src per slot
__device__ float g_ce[NE * 4];        // CSR: exp-scores per slot (float4)
__device__ int   g_idx64;

// ---- packed f32x2 helpers (exact rn fp32, 2 MACs per instruction) ----
typedef unsigned long long u64;
__device__ __forceinline__ u64 pk2(float lo, float hi) {
    u64 d; asm("mov.b64 %0,{%1,%2};" : "=l"(d) : "f"(lo), "f"(hi)); return d;
}
__device__ __forceinline__ u64 bc2(float v) { return pk2(v, v); }
__device__ __forceinline__ void upk2(u64 d, float& lo, float& hi) {
    asm("mov.b64 {%0,%1},%2;" : "=f"(lo), "=f"(hi) : "l"(d));
}
__device__ __forceinline__ u64 fma2(u64 a, u64 b, u64 c) {
    u64 d; asm("fma.rn.f32x2 %0,%1,%2,%3;" : "=l"(d) : "l"(a), "l"(b), "l"(c));
    return d;
}
__device__ __forceinline__ u64 add2(u64 a, u64 b) {
    u64 d; asm("add.rn.f32x2 %0,%1,%2;" : "=l"(d) : "l"(a), "l"(b)); return d;
}

__device__ __forceinline__ int edge_idx(const void* ei, long long pos) {
    if (g_idx64) return (int)((const long long*)ei)[pos];
    return ((const int*)ei)[pos];
}

// ---- fused: dtype probe + zero histogram ----
__global__ void k_init(const void* ei) {
    int i = blockIdx.x * blockDim.x + threadIdx.x;
    if (i < NN) g_cnt[i] = 0;
    if (i == 0) {
        const long long* p = (const long long*)ei;
        bool ok = true;
        for (int k = 0; k < 4; k++) {
            long long v = p[k];
            if (v < 0 || v >= NN) ok = false;
        }
        g_idx64 = ok ? 1 : 0;
    }
}

// ---- node precompute: h = xW+b ; a = h @ attn_w ----
#define ROWS_K1 16
__global__ __launch_bounds__(256) void k_node(const float* __restrict__ x,
                                              const float* __restrict__ Ww,
                                              const float* __restrict__ Wb,
                                              const float* __restrict__ aw) {
    __shared__ float xs[ROWS_K1][C];
    __shared__ float hs[ROWS_K1][C];
    const int base = blockIdx.x * ROWS_K1;
    const int t = threadIdx.x;

#pragma unroll
    for (int k = 0; k < 4; k++) {
        int idx = t + k * 256;
        xs[idx >> 6][idx & 63] = x[(base + (idx >> 6)) * C + (idx & 63)];
    }
    __syncthreads();

    {
        int j = t & 63;
        int r0 = (t >> 6) * 4;
        // packed: rows (0,1) and (2,3) share multiplier w
        u64 p01 = 0, p23 = 0;
#pragma unroll 8
        for (int c = 0; c < C; c++) {
            u64 w2 = bc2(__ldg(&Ww[c * C + j]));
            p01 = fma2(pk2(xs[r0 + 0][c], xs[r0 + 1][c]), w2, p01);
            p23 = fma2(pk2(xs[r0 + 2][c], xs[r0 + 3][c]), w2, p23);
        }
        float a0, a1, a2, a3;
        upk2(p01, a0, a1); upk2(p23, a2, a3);
        float b = __ldg(&Wb[j]);
        a0 += b; a1 += b; a2 += b; a3 += b;
        hs[r0 + 0][j] = a0; hs[r0 + 1][j] = a1;
        hs[r0 + 2][j] = a2; hs[r0 + 3][j] = a3;
        g_h[(base + r0 + 0) * C + j] = a0;
        g_h[(base + r0 + 1) * C + j] = a1;
        g_h[(base + r0 + 2) * C + j] = a2;
        g_h[(base + r0 + 3) * C + j] = a3;
    }
    __syncthreads();

    if (t < 128) {
        int r = t >> 3, k = t & 7;
        int hh = k & 3;
        int off = (k < 4) ? 0 : C;
        float acc = 0.f;
#pragma unroll 8
        for (int c = 0; c < C; c++)
            acc = fmaf(hs[r][c], __ldg(&aw[(off + c) * H + hh]), acc);
        g_a[(base + r) * 8 + k] = acc;
    }
}

// ---- in-degree histogram ----
__global__ __launch_bounds__(256) void k_hist(const void* __restrict__ ei) {
    int e = blockIdx.x * blockDim.x + threadIdx.x;
    if (e >= NE) return;
    int dst = edge_idx(ei, (long long)NE + e);
    atomicAdd(&g_cnt[dst], 1);
}

// ---- scan phase A ----
__global__ __launch_bounds__(1024) void k_scanA() {
    __shared__ int sh[1024];
    int b = blockIdx.x, t = threadIdx.x;
    int idx = b * 1024 + t;
    int v = (idx < NN) ? g_cnt[idx] : 0;
    sh[t] = v;
    __syncthreads();
#pragma unroll
    for (int o = 1; o < 1024; o <<= 1) {
        int x = (t >= o) ? sh[t - o] : 0;
        __syncthreads();
        sh[t] += x;
        __syncthreads();
    }
    if (idx < NN) g_off[idx] = sh[t] - v;
    if (t == 1023) g_btot[b] = sh[1023];
}

// ---- scan phase B ----
__global__ __launch_bounds__(1024) void k_scanB() {
    __shared__ int bt[NB_SCAN];
    int b = blockIdx.x, t = threadIdx.x;
    if (t < NB_SCAN) bt[t] = g_btot[t];
    __syncthreads();
    int s = 0;
    for (int i = 0; i < b; i++) s += bt[i];
    int idx = b * 1024 + t;
    if (idx < NN) {
        int o = g_off[idx] + s;
        g_off[idx] = o;
        g_cur[idx] = o;
    }
    if (b == 0 && t == 0) g_off[NN] = NE;
}

// ---- fused score + CSR scatter ----
__global__ __launch_bounds__(256) void k_scatter(const void* __restrict__ ei,
                                                 const float* __restrict__ et,
                                                 const int* __restrict__ ct,
                                                 const float* __restrict__ ab,
                                                 const float* __restrict__ dr) {
    int e = blockIdx.x * blockDim.x + threadIdx.x;
    if (e >= NE) return;
    int src = edge_idx(ei, e);
    int dst = edge_idx(ei, (long long)NE + e);

    float lam = log1pf(__expf(dr[0]));            // softplus
    float dt = (float)ct[0] - et[e];
    float decay = __expf(-lam * dt);

    float4 as = *(const float4*)&g_a[src * 8];
    float4 ad = *(const float4*)&g_a[dst * 8 + 4];
    float s[4];
    s[0] = as.x + ad.x + __ldg(&ab[0]);
    s[1] = as.y + ad.y + __ldg(&ab[1]);
    s[2] = as.z + ad.z + __ldg(&ab[2]);
    s[3] = as.w + ad.w + __ldg(&ab[3]);
#pragma unroll
    for (int h = 0; h < 4; h++) {
        float l = s[h];
        l = (l > 0.f) ? l : 0.2f * l;             // LeakyReLU(0.2)
        s[h] = __expf(l * decay);
    }
    int pos = atomicAdd(&g_cur[dst], 1);
    g_csrc[pos] = src;
    *(float4*)&g_ce[pos * 4] = make_float4(s[0], s[1], s[2], s[3]);
}

// ---- FUSED aggregation + projection GEMM + bias/residual/LN/ReLU ----
// R3 structure (warp x 4 nodes serial agg) + packed f32x2 math everywhere.
// Lane covers columns (2*lane, 2*lane+1): h gathered as float2 (LDG.64).
#define TB 32
#define UPAD 260
union F4U2 { float4 f; struct { u64 lo, hi; } u; };

__global__ __launch_bounds__(256) void k_aggemm(const float* __restrict__ pw,
                                                const float* __restrict__ pb,
                                                const float* __restrict__ x,
                                                const float* __restrict__ lg,
                                                const float* __restrict__ lb,
                                                float* __restrict__ out) {
    __shared__ float us[TB][UPAD];   // u[node_local][q], q = h*64+c
    __shared__ float ws[32][68];     // W2 chunk [kk][j], reused for z in epilogue
    const int t = threadIdx.x;
    const int w = t >> 5, lane = t & 31;
    const int base = blockIdx.x * TB;
    const int c0 = lane * 2;

    // ---- phase 1: CSR aggregation, 4 nodes per warp, packed f32x2 ----
#pragma unroll
    for (int rr = 0; rr < 4; rr++) {
        int r = w * 4 + rr;
        int n = base + r;
        int i = g_off[n], end = g_off[n + 1];

        u64 ac0 = 0, ac1 = 0, ac2 = 0, ac3 = 0;   // per-head packed col-pair
        u64 s01 = 0, s23 = 0;                      // packed exp-sums

        for (; i + 2 <= end; i += 2) {
            int sa = __ldg(&g_csrc[i]);
            int sb = __ldg(&g_csrc[i + 1]);
            float4 ea = __ldg((const float4*)&g_ce[i * 4]);
            float4 eb = __ldg((const float4*)&g_ce[i * 4 + 4]);
            float2 hva = __ldg((const float2*)&g_h[sa * C + c0]);
            float2 hvb = __ldg((const float2*)&g_h[sb * C + c0]);
            u64 hpa = pk2(hva.x, hva.y);
            u64 hpb = pk2(hvb.x, hvb.y);
            ac0 = fma2(bc2(ea.x), hpa, ac0);
            ac1 = fma2(bc2(ea.y), hpa, ac1);
            ac2 = fma2(bc2(ea.z), hpa, ac2);
            ac3 = fma2(bc2(ea.w), hpa, ac3);
            s01 = add2(s01, pk2(ea.x, ea.y));
            s23 = add2(s23, pk2(ea.z, ea.w));
            ac0 = fma2(bc2(eb.x), hpb, ac0);
            ac1 = fma2(bc2(eb.y), hpb, ac1);
            ac2 = fma2(bc2(eb.z), hpb, ac2);
            ac3 = fma2(bc2(eb.w), hpb, ac3);
            s01 = add2(s01, pk2(eb.x, eb.y));
            s23 = add2(s23, pk2(eb.z, eb.w));
        }
        if (i < end) {
            int sa = __ldg(&g_csrc[i]);
            float4 ea = __ldg((const float4*)&g_ce[i * 4]);
            float2 hva = __ldg((const float2*)&g_h[sa * C + c0]);
            u64 hpa = pk2(hva.x, hva.y);
            ac0 = fma2(bc2(ea.x), hpa, ac0);
            ac1 = fma2(bc2(ea.y), hpa, ac1);
            ac2 = fma2(bc2(ea.z), hpa, ac2);
            ac3 = fma2(bc2(ea.w), hpa, ac3);
            s01 = add2(s01, pk2(ea.x, ea.y));
            s23 = add2(s23, pk2(ea.z, ea.w));
        }
        float s0, s1, s2, s3;
        upk2(s01, s0, s1); upk2(s23, s2, s3);
        float r0 = 1.f / (s0 + 1e-8f);
        float r1 = 1.f / (s1 + 1e-8f);
        float r2 = 1.f / (s2 + 1e-8f);
        float r3 = 1.f / (s3 + 1e-8f);
        float lo, hi;
        upk2(ac0, lo, hi);
        *(float2*)&us[r][0 * 64 + c0] = make_float2(lo * r0, hi * r0);
        upk2(ac1, lo, hi);
        *(float2*)&us[r][1 * 64 + c0] = make_float2(lo * r1, hi * r1);
        upk2(ac2, lo, hi);
        *(float2*)&us[r][2 * 64 + c0] = make_float2(lo * r2, hi * r2);
        upk2(ac3, lo, hi);
        *(float2*)&us[r][3 * 64 + c0] = make_float2(lo * r3, hi * r3);
    }
    __syncthreads();

    // ---- phase 2: GEMM 32x64, K=256 in chunks of 32, packed f32x2 ----
    const int tx = t & 15, ty = t >> 4;   // cols tx*4, rows ty*2
    u64 acc[2][2];                         // [row][colpair]
    acc[0][0] = 0; acc[0][1] = 0; acc[1][0] = 0; acc[1][1] = 0;

    for (int kc = 0; kc < 8; kc++) {
#pragma unroll
        for (int rr = 0; rr < 2; rr++) {
            int kk = ty * 2 + rr;
            int q = kc * 32 + kk;
            int row = ((q & 63) << 2) + (q >> 6);
            float4 wv = __ldg((const float4*)&pw[row * 64 + tx * 4]);
            ws[kk][tx * 4 + 0] = wv.x; ws[kk][tx * 4 + 1] = wv.y;
            ws[kk][tx * 4 + 2] = wv.z; ws[kk][tx * 4 + 3] = wv.w;
        }
        __syncthreads();

#pragma unroll 8
        for (int k4 = 0; k4 < 8; k4++) {
            float4 a0 = *(const float4*)&us[ty * 2 + 0][kc * 32 + k4 * 4];
            float4 a1 = *(const float4*)&us[ty * 2 + 1][kc * 32 + k4 * 4];
            F4U2 b0, b1, b2, b3;
            b0.f = *(const float4*)&ws[k4 * 4 + 0][tx * 4];
            b1.f = *(const float4*)&ws[k4 * 4 + 1][tx * 4];
            b2.f = *(const float4*)&ws[k4 * 4 + 2][tx * 4];
            b3.f = *(const float4*)&ws[k4 * 4 + 3][tx * 4];
            u64 m;
            m = bc2(a0.x);
            acc[0][0] = fma2(m, b0.u.lo, acc[0][0]);
            acc[0][1] = fma2(m, b0.u.hi, acc[0][1]);
            m = bc2(a1.x);
            acc[1][0] = fma2(m, b0.u.lo, acc[1][0]);
            acc[1][1] = fma2(m, b0.u.hi, acc[1][1]);
            m = bc2(a0.y);
            acc[0][0] = fma2(m, b1.u.lo, acc[0][0]);
            acc[0][1] = fma2(m, b1.u.hi, acc[0][1]);
            m = bc2(a1.y);
            acc[1][0] = fma2(m, b1.u.lo, acc[1][0]);
            acc[1][1] = fma2(m, b1.u.hi, acc[1][1]);
            m = bc2(a0.z);
            acc[0][0] = fma2(m, b2.u.lo, acc[0][0]);
            acc[0][1] = fma2(m, b2.u.hi, acc[0][1]);
            m = bc2(a1.z);
            acc[1][0] = fma2(m, b2.u.lo, acc[1][0]);
            acc[1][1] = fma2(m, b2.u.hi, acc[1][1]);
            m = bc2(a0.w);
            acc[0][0] = fma2(m, b3.u.lo, acc[0][0]);
            acc[0][1] = fma2(m, b3.u.hi, acc[0][1]);
            m = bc2(a1.w);
            acc[1][0] = fma2(m, b3.u.lo, acc[1][0]);
            acc[1][1] = fma2(m, b3.u.hi, acc[1][1]);
        }
        __syncthreads();
    }

    // ---- epilogue: z = acc + pb + x into ws, then LN + ReLU ----
    float4 bias = __ldg((const float4*)&pb[tx * 4]);
#pragma unroll
    for (int i = 0; i < 2; i++) {
        int node = base + ty * 2 + i;
        float4 xv = *(const float4*)&x[node * 64 + tx * 4];
        float q0, q1, q2, q3;
        upk2(acc[i][0], q0, q1);
        upk2(acc[i][1], q2, q3);
        ws[ty * 2 + i][tx * 4 + 0] = q0 + bias.x + xv.x;
        ws[ty * 2 + i][tx * 4 + 1] = q1 + bias.y + xv.y;
        ws[ty * 2 + i][tx * 4 + 2] = q2 + bias.z + xv.z;
        ws[ty * 2 + i][tx * 4 + 3] = q3 + bias.w + xv.w;
    }
    __syncthreads();

#pragma unroll
    for (int rr = 0; rr < 4; rr++) {
        int row = w * 4 + rr;
        int node = base + row;
        float z0 = ws[row][lane];
        float z1 = ws[row][32 + lane];
        float s = z0 + z1;
#pragma unroll
        for (int o = 16; o; o >>= 1) s += __shfl_xor_sync(0xffffffffu, s, o);
        float mu = s * (1.f / 64.f);
        float d0 = z0 - mu, d1 = z1 - mu;
        float v = d0 * d0 + d1 * d1;
#pragma unroll
        for (int o = 16; o; o >>= 1) v += __shfl_xor_sync(0xffffffffu, v, o);
        float inv = rsqrtf(v * (1.f / 64.f) + 1e-5f);
        float y0 = __ldg(&lg[lane])      * d0 * inv + __ldg(&lb[lane]);
        float y1 = __ldg(&lg[32 + lane]) * d1 * inv + __ldg(&lb[32 + lane]);
        out[node * 64 + lane]      = fmaxf(y0, 0.f);
        out[node * 64 + 32 + lane] = fmaxf(y1, 0.f);
    }
}

extern "C" void kernel_launch(void* const* d_in, const int* in_sizes, int n_in,
                              void* d_out, int out_size) {
    const float* x  = (const float*)d_in[0];
    const void*  ei = d_in[1];
    const float* et = (const float*)d_in[2];
    const int*   ct = (const int*)d_in[3];
    const float* Ww = (const float*)d_in[4];
    const float* Wb = (const float*)d_in[5];
    const float* aw = (const float*)d_in[6];
    const float* ab = (const float*)d_in[7];
    const float* dr = (const float*)d_in[8];
    const float* pw = (const float*)d_in[9];
    const float* pb = (const float*)d_in[10];
    const float* lg = (const float*)d_in[11];
    const float* lb = (const float*)d_in[12];
    float* out = (float*)d_out;

    k_init<<<(NN + 255) / 256, 256>>>(ei);
    k_node<<<NN / ROWS_K1, 256>>>(x, Ww, Wb, aw);
    k_hist<<<NE / 256, 256>>>(ei);
    k_scanA<<<NB_SCAN, 1024>>>();
    k_scanB<<<NB_SCAN, 1024>>>();
    k_scatter<<<NE / 256, 256>>>(ei, et, ct, ab, dr);
    k_aggemm<<<NN / TB, 256>>>(pw, pb, x, lg, lb, out);
}

// round 9
// speedup vs baseline: 1.3326x; 1.0653x over previous
#include <cuda_runtime.h>

#define NN 100000
#define NE 800000
#define C 64
#define H 4
#define NB_SCAN 98   // ceil(NN/1024)
#define NPAD 100096  // 782 * 128, padded row count for k_gemm

// ---- scratch (allocation-free: __device__ globals) ----
__device__ float g_h[NN * C];         // h = xW + b
__device__ float g_a[NN * 8];         // a_src[0..3], a_dst[0..3]
__device__ int   g_cnt[NN];           // in-degree histogram
__device__ int   g_off[NN + 1];       // CSR offsets
__device__ int   g_cur[NN];           // scatter cursors
__device__ int   g_btot[NB_SCAN];     // scan block totals
__device__ int   g_csrc[NE];          // CSR: src per slot
__device__ float g_ce[NE * 4];        // CSR: exp-scores per slot (float4)
__device__ float g_u[NPAD * 256];     // normalized aggregate, q = h*64+c
__device__ int   g_idx64;

// ---- packed f32x2 helpers (exact rn fp32, 2 MACs per instruction) ----
typedef unsigned long long u64;
__device__ __forceinline__ u64 pk2(float lo, float hi) {
    u64 d; asm("mov.b64 %0,{%1,%2};" : "=l"(d) : "f"(lo), "f"(hi)); return d;
}
__device__ __forceinline__ u64 bc2(float v) { return pk2(v, v); }
__device__ __forceinline__ void upk2(u64 d, float& lo, float& hi) {
    asm("mov.b64 {%0,%1},%2;" : "=f"(lo), "=f"(hi) : "l"(d));
}
__device__ __forceinline__ u64 fma2(u64 a, u64 b, u64 c) {
    u64 d; asm("fma.rn.f32x2 %0,%1,%2,%3;" : "=l"(d) : "l"(a), "l"(b), "l"(c));
    return d;
}
__device__ __forceinline__ u64 add2(u64 a, u64 b) {
    u64 d; asm("add.rn.f32x2 %0,%1,%2;" : "=l"(d) : "l"(a), "l"(b)); return d;
}
union F4U2 { float4 f; struct { u64 lo, hi; } u; };

__device__ __forceinline__ int edge_idx(const void* ei, long long pos) {
    if (g_idx64) return (int)((const long long*)ei)[pos];
    return ((const int*)ei)[pos];
}

// ---- fused: dtype probe + zero histogram ----
__global__ void k_init(const void* ei) {
    int i = blockIdx.x * blockDim.x + threadIdx.x;
    if (i < NN) g_cnt[i] = 0;
    if (i == 0) {
        const long long* p = (const long long*)ei;
        bool ok = true;
        for (int k = 0; k < 4; k++) {
            long long v = p[k];
            if (v < 0 || v >= NN) ok = false;
        }
        g_idx64 = ok ? 1 : 0;
    }
}

// ---- node precompute: h = xW+b ; a = h @ attn_w ----
#define ROWS_K1 16
__global__ __launch_bounds__(256) void k_node(const float* __restrict__ x,
                                              const float* __restrict__ Ww,
                                              const float* __restrict__ Wb,
                                              const float* __restrict__ aw) {
    __shared__ float xs[ROWS_K1][C];
    __shared__ float hs[ROWS_K1][C];
    const int base = blockIdx.x * ROWS_K1;
    const int t = threadIdx.x;

#pragma unroll
    for (int k = 0; k < 4; k++) {
        int idx = t + k * 256;
        xs[idx >> 6][idx & 63] = x[(base + (idx >> 6)) * C + (idx & 63)];
    }
    __syncthreads();

    {
        int j = t & 63;
        int r0 = (t >> 6) * 4;
        u64 p01 = 0, p23 = 0;
#pragma unroll 8
        for (int c = 0; c < C; c++) {
            u64 w2 = bc2(__ldg(&Ww[c * C + j]));
            p01 = fma2(pk2(xs[r0 + 0][c], xs[r0 + 1][c]), w2, p01);
            p23 = fma2(pk2(xs[r0 + 2][c], xs[r0 + 3][c]), w2, p23);
        }
        float a0, a1, a2, a3;
        upk2(p01, a0, a1); upk2(p23, a2, a3);
        float b = __ldg(&Wb[j]);
        a0 += b; a1 += b; a2 += b; a3 += b;
        hs[r0 + 0][j] = a0; hs[r0 + 1][j] = a1;
        hs[r0 + 2][j] = a2; hs[r0 + 3][j] = a3;
        g_h[(base + r0 + 0) * C + j] = a0;
        g_h[(base + r0 + 1) * C + j] = a1;
        g_h[(base + r0 + 2) * C + j] = a2;
        g_h[(base + r0 + 3) * C + j] = a3;
    }
    __syncthreads();

    if (t < 128) {
        int r = t >> 3, k = t & 7;
        int hh = k & 3;
        int off = (k < 4) ? 0 : C;
        float acc = 0.f;
#pragma unroll 8
        for (int c = 0; c < C; c++)
            acc = fmaf(hs[r][c], __ldg(&aw[(off + c) * H + hh]), acc);
        g_a[(base + r) * 8 + k] = acc;
    }
}

// ---- in-degree histogram ----
__global__ __launch_bounds__(256) void k_hist(const void* __restrict__ ei) {
    int e = blockIdx.x * blockDim.x + threadIdx.x;
    if (e >= NE) return;
    int dst = edge_idx(ei, (long long)NE + e);
    atomicAdd(&g_cnt[dst], 1);
}

// ---- scan phase A ----
__global__ __launch_bounds__(1024) void k_scanA() {
    __shared__ int sh[1024];
    int b = blockIdx.x, t = threadIdx.x;
    int idx = b * 1024 + t;
    int v = (idx < NN) ? g_cnt[idx] : 0;
    sh[t] = v;
    __syncthreads();
#pragma unroll
    for (int o = 1; o < 1024; o <<= 1) {
        int x = (t >= o) ? sh[t - o] : 0;
        __syncthreads();
        sh[t] += x;
        __syncthreads();
    }
    if (idx < NN) g_off[idx] = sh[t] - v;
    if (t == 1023) g_btot[b] = sh[1023];
}

// ---- scan phase B ----
__global__ __launch_bounds__(1024) void k_scanB() {
    __shared__ int bt[NB_SCAN];
    int b = blockIdx.x, t = threadIdx.x;
    if (t < NB_SCAN) bt[t] = g_btot[t];
    __syncthreads();
    int s = 0;
    for (int i = 0; i < b; i++) s += bt[i];
    int idx = b * 1024 + t;
    if (idx < NN) {
        int o = g_off[idx] + s;
        g_off[idx] = o;
        g_cur[idx] = o;
    }
    if (b == 0 && t == 0) g_off[NN] = NE;
}

// ---- fused score + CSR scatter ----
__global__ __launch_bounds__(256) void k_scatter(const void* __restrict__ ei,
                                                 const float* __restrict__ et,
                                                 const int* __restrict__ ct,
                                                 const float* __restrict__ ab,
                                                 const float* __restrict__ dr) {
    int e = blockIdx.x * blockDim.x + threadIdx.x;
    if (e >= NE) return;
    int src = edge_idx(ei, e);
    int dst = edge_idx(ei, (long long)NE + e);

    float lam = log1pf(__expf(dr[0]));            // softplus
    float dt = (float)ct[0] - et[e];
    float decay = __expf(-lam * dt);

    float4 as = *(const float4*)&g_a[src * 8];
    float4 ad = *(const float4*)&g_a[dst * 8 + 4];
    float s[4];
    s[0] = as.x + ad.x + __ldg(&ab[0]);
    s[1] = as.y + ad.y + __ldg(&ab[1]);
    s[2] = as.z + ad.z + __ldg(&ab[2]);
    s[3] = as.w + ad.w + __ldg(&ab[3]);
#pragma unroll
    for (int h = 0; h < 4; h++) {
        float l = s[h];
        l = (l > 0.f) ? l : 0.2f * l;             // LeakyReLU(0.2)
        s[h] = __expf(l * decay);
    }
    int pos = atomicAdd(&g_cur[dst], 1);
    g_csrc[pos] = src;
    *(float4*)&g_ce[pos * 4] = make_float4(s[0], s[1], s[2], s[3]);
}

// ---- aggregation: warp per node, zero smem, 4-edge unroll, packed f32x2 ----
__global__ __launch_bounds__(256) void k_agg() {
    int n = blockIdx.x * 8 + (threadIdx.x >> 5);
    int lane = threadIdx.x & 31;
    const int c0 = lane * 2;
    int i = g_off[n];
    const int end = g_off[n + 1];

    u64 ac0 = 0, ac1 = 0, ac2 = 0, ac3 = 0;
    u64 s01 = 0, s23 = 0;

    for (; i + 4 <= end; i += 4) {
        int sa = __ldg(&g_csrc[i]);
        int sb = __ldg(&g_csrc[i + 1]);
        int sc = __ldg(&g_csrc[i + 2]);
        int sd = __ldg(&g_csrc[i + 3]);
        float4 ea = __ldg((const float4*)&g_ce[i * 4]);
        float4 eb = __ldg((const float4*)&g_ce[i * 4 + 4]);
        float4 ec = __ldg((const float4*)&g_ce[i * 4 + 8]);
        float4 ed = __ldg((const float4*)&g_ce[i * 4 + 12]);
        float2 hva = __ldg((const float2*)&g_h[sa * C + c0]);
        float2 hvb = __ldg((const float2*)&g_h[sb * C + c0]);
        float2 hvc = __ldg((const float2*)&g_h[sc * C + c0]);
        float2 hvd = __ldg((const float2*)&g_h[sd * C + c0]);
        u64 hpa = pk2(hva.x, hva.y);
        u64 hpb = pk2(hvb.x, hvb.y);
        u64 hpc = pk2(hvc.x, hvc.y);
        u64 hpd = pk2(hvd.x, hvd.y);
        ac0 = fma2(bc2(ea.x), hpa, ac0);
        ac1 = fma2(bc2(ea.y), hpa, ac1);
        ac2 = fma2(bc2(ea.z), hpa, ac2);
        ac3 = fma2(bc2(ea.w), hpa, ac3);
        s01 = add2(s01, pk2(ea.x, ea.y));
        s23 = add2(s23, pk2(ea.z, ea.w));
        ac0 = fma2(bc2(eb.x), hpb, ac0);
        ac1 = fma2(bc2(eb.y), hpb, ac1);
        ac2 = fma2(bc2(eb.z), hpb, ac2);
        ac3 = fma2(bc2(eb.w), hpb, ac3);
        s01 = add2(s01, pk2(eb.x, eb.y));
        s23 = add2(s23, pk2(eb.z, eb.w));
        ac0 = fma2(bc2(ec.x), hpc, ac0);
        ac1 = fma2(bc2(ec.y), hpc, ac1);
        ac2 = fma2(bc2(ec.z), hpc, ac2);
        ac3 = fma2(bc2(ec.w), hpc, ac3);
        s01 = add2(s01, pk2(ec.x, ec.y));
        s23 = add2(s23, pk2(ec.z, ec.w));
        ac0 = fma2(bc2(ed.x), hpd, ac0);
        ac1 = fma2(bc2(ed.y), hpd, ac1);
        ac2 = fma2(bc2(ed.z), hpd, ac2);
        ac3 = fma2(bc2(ed.w), hpd, ac3);
        s01 = add2(s01, pk2(ed.x, ed.y));
        s23 = add2(s23, pk2(ed.z, ed.w));
    }
    for (; i < end; i++) {
        int sa = __ldg(&g_csrc[i]);
        float4 ea = __ldg((const float4*)&g_ce[i * 4]);
        float2 hva = __ldg((const float2*)&g_h[sa * C + c0]);
        u64 hpa = pk2(hva.x, hva.y);
        ac0 = fma2(bc2(ea.x), hpa, ac0);
        ac1 = fma2(bc2(ea.y), hpa, ac1);
        ac2 = fma2(bc2(ea.z), hpa, ac2);
        ac3 = fma2(bc2(ea.w), hpa, ac3);
        s01 = add2(s01, pk2(ea.x, ea.y));
        s23 = add2(s23, pk2(ea.z, ea.w));
    }
    float s0, s1, s2, s3;
    upk2(s01, s0, s1); upk2(s23, s2, s3);
    float r0 = 1.f / (s0 + 1e-8f);
    float r1 = 1.f / (s1 + 1e-8f);
    float r2 = 1.f / (s2 + 1e-8f);
    float r3 = 1.f / (s3 + 1e-8f);
    float lo, hi;
    float* u = &g_u[n * 256];
    upk2(ac0, lo, hi); *(float2*)&u[0 * 64 + c0] = make_float2(lo * r0, hi * r0);
    upk2(ac1, lo, hi); *(float2*)&u[1 * 64 + c0] = make_float2(lo * r1, hi * r1);
    upk2(ac2, lo, hi); *(float2*)&u[2 * 64 + c0] = make_float2(lo * r2, hi * r2);
    upk2(ac3, lo, hi); *(float2*)&u[3 * 64 + c0] = make_float2(lo * r3, hi * r3);
}

// ---- GEMM u(128-row tile x 256) @ W2(256x64) + bias/residual/LN/ReLU ----
// 256 threads, 8x4 micro-tile. As k-major (stride 132), Bs k-major (stride 68).
#define AS_STRIDE 132
__global__ __launch_bounds__(256) void k_gemm(const float* __restrict__ pw,
                                              const float* __restrict__ pb,
                                              const float* __restrict__ x,
                                              const float* __restrict__ lg,
                                              const float* __restrict__ lb,
                                              float* __restrict__ out) {
    __shared__ float sm[128 * 68];                 // z buffer; aliases As+Bs
    float* As = sm;                                // [32][AS_STRIDE]
    float* Bs = sm + 32 * AS_STRIDE;               // [32][68]
    const int t = threadIdx.x;
    const int tx = t & 15, ty = t >> 4;            // cols tx*4.., rows ty*8..
    const int w = t >> 5, lane = t & 31;
    const int base = blockIdx.x * 128;

    const int ar = t >> 1;                         // A-load row 0..127
    const int ak = (t & 1) * 16;                   // A-load k offset

    u64 acc[8][2];
#pragma unroll
    for (int r = 0; r < 8; r++) { acc[r][0] = 0; acc[r][1] = 0; }

    for (int kc = 0; kc < 8; kc++) {
        // stage A transposed: As[k][row], 16 floats per thread
        {
            const float* src = &g_u[(base + ar) * 256 + kc * 32 + ak];
            float4 v0 = __ldg((const float4*)&src[0]);
            float4 v1 = __ldg((const float4*)&src[4]);
            float4 v2 = __ldg((const float4*)&src[8]);
            float4 v3 = __ldg((const float4*)&src[12]);
            float vv[16] = {v0.x, v0.y, v0.z, v0.w, v1.x, v1.y, v1.z, v1.w,
                            v2.x, v2.y, v2.z, v2.w, v3.x, v3.y, v3.z, v3.w};
#pragma unroll
            for (int i = 0; i < 16; i++)
                As[(ak + i) * AS_STRIDE + ar] = vv[i];
        }
        // stage B: Bs[kk][j] = W2[kc*32+kk][j] (permuted proj_w)
#pragma unroll
        for (int rr = 0; rr < 2; rr++) {
            int kk = ty * 2 + rr;
            int q = kc * 32 + kk;
            int row = ((q & 63) << 2) + (q >> 6);
            float4 wv = __ldg((const float4*)&pw[row * 64 + tx * 4]);
            Bs[kk * 68 + tx * 4 + 0] = wv.x; Bs[kk * 68 + tx * 4 + 1] = wv.y;
            Bs[kk * 68 + tx * 4 + 2] = wv.z; Bs[kk * 68 + tx * 4 + 3] = wv.w;
        }
        __syncthreads();

#pragma unroll 4
        for (int k = 0; k < 32; k++) {
            float4 a0 = *(const float4*)&As[k * AS_STRIDE + ty * 8];
            float4 a1 = *(const float4*)&As[k * AS_STRIDE + ty * 8 + 4];
            F4U2 b; b.f = *(const float4*)&Bs[k * 68 + tx * 4];
            u64 m;
            m = bc2(a0.x); acc[0][0] = fma2(m, b.u.lo, acc[0][0]); acc[0][1] = fma2(m, b.u.hi, acc[0][1]);
            m = bc2(a0.y); acc[1][0] = fma2(m, b.u.lo, acc[1][0]); acc[1][1] = fma2(m, b.u.hi, acc[1][1]);
            m = bc2(a0.z); acc[2][0] = fma2(m, b.u.lo, acc[2][0]); acc[2][1] = fma2(m, b.u.hi, acc[2][1]);
            m = bc2(a0.w); acc[3][0] = fma2(m, b.u.lo, acc[3][0]); acc[3][1] = fma2(m, b.u.hi, acc[3][1]);
            m = bc2(a1.x); acc[4][0] = fma2(m, b.u.lo, acc[4][0]); acc[4][1] = fma2(m, b.u.hi, acc[4][1]);
            m = bc2(a1.y); acc[5][0] = fma2(m, b.u.lo, acc[5][0]); acc[5][1] = fma2(m, b.u.hi, acc[5][1]);
            m = bc2(a1.z); acc[6][0] = fma2(m, b.u.lo, acc[6][0]); acc[6][1] = fma2(m, b.u.hi, acc[6][1]);
            m = bc2(a1.w); acc[7][0] = fma2(m, b.u.lo, acc[7][0]); acc[7][1] = fma2(m, b.u.hi, acc[7][1]);
        }
        __syncthreads();
    }

    // ---- epilogue: z = acc + pb + x into sm[128][68], then LN + ReLU ----
    float4 bias = __ldg((const float4*)&pb[tx * 4]);
#pragma unroll
    for (int r = 0; r < 8; r++) {
        int row = ty * 8 + r;
        int node = base + row;
        float4 xv = make_float4(0.f, 0.f, 0.f, 0.f);
        if (node < NN)
            xv = *(const float4*)&x[node * 64 + tx * 4];
        float q0, q1, q2, q3;
        upk2(acc[r][0], q0, q1);
        upk2(acc[r][1], q2, q3);
        sm[row * 68 + tx * 4 + 0] = q0 + bias.x + xv.x;
        sm[row * 68 + tx * 4 + 1] = q1 + bias.y + xv.y;
        sm[row * 68 + tx * 4 + 2] = q2 + bias.z + xv.z;
        sm[row * 68 + tx * 4 + 3] = q3 + bias.w + xv.w;
    }
    __syncthreads();

#pragma unroll
    for (int rr = 0; rr < 16; rr++) {
        int row = w * 16 + rr;
        int node = base + row;
        float z0 = sm[row * 68 + lane];
        float z1 = sm[row * 68 + 32 + lane];
        float s = z0 + z1;
#pragma unroll
        for (int o = 16; o; o >>= 1) s += __shfl_xor_sync(0xffffffffu, s, o);
        float mu = s * (1.f / 64.f);
        float d0 = z0 - mu, d1 = z1 - mu;
        float v = d0 * d0 + d1 * d1;
#pragma unroll
        for (int o = 16; o; o >>= 1) v += __shfl_xor_sync(0xffffffffu, v, o);
        float inv = rsqrtf(v * (1.f / 64.f) + 1e-5f);
        float y0 = __ldg(&lg[lane])      * d0 * inv + __ldg(&lb[lane]);
        float y1 = __ldg(&lg[32 + lane]) * d1 * inv + __ldg(&lb[32 + lane]);
        if (node < NN) {
            out[node * 64 + lane]      = fmaxf(y0, 0.f);
            out[node * 64 + 32 + lane] = fmaxf(y1, 0.f);
        }
    }
}

extern "C" void kernel_launch(void* const* d_in, const int* in_sizes, int n_in,
                              void* d_out, int out_size) {
    const float* x  = (const float*)d_in[0];
    const void*  ei = d_in[1];
    const float* et = (const float*)d_in[2];
    const int*   ct = (const int*)d_in[3];
    const float* Ww = (const float*)d_in[4];
    const float* Wb = (const float*)d_in[5];
    const float* aw = (const float*)d_in[6];
    const float* ab = (const float*)d_in[7];
    const float* dr = (const float*)d_in[8];
    const float* pw = (const float*)d_in[9];
    const float* pb = (const float*)d_in[10];
    const float* lg = (const float*)d_in[11];
    const float* lb = (const float*)d_in[12];
    float* out = (float*)d_out;

    k_init<<<(NN + 255) / 256, 256>>>(ei);
    k_node<<<NN / ROWS_K1, 256>>>(x, Ww, Wb, aw);
    k_hist<<<NE / 256, 256>>>(ei);
    k_scanA<<<NB_SCAN, 1024>>>();
    k_scanB<<<NB_SCAN, 1024>>>();
    k_scatter<<<NE / 256, 256>>>(ei, et, ct, ab, dr);
    k_agg<<<NN / 8, 256>>>();
    k_gemm<<<NPAD / 128, 256>>>(pw, pb, x, lg, lb, out);
}